// round 15
// baseline (speedup 1.0000x reference)
#include <cuda_runtime.h>
#include <cuda_bf16.h>
#include <cstdint>
#include <cstddef>

#define B_    1024
#define N_    64
#define F_    1024
#define H1_   256
#define H2_   128
#define NC_   128
#define ALPHA_ 0.2f
#define EPS_  1e-5f

// ---------------- scratch (device globals; no allocations) ----------------
__device__ float g_nbh [B_ * N_ * H1_];   // 64 MB  layer-1 neighbor features
__device__ float g_x1  [B_ * H1_];
__device__ float g_x2  [B_ * H2_];
__device__ float g_u1  [F_];              // W1^T a11
__device__ float g_u2  [H1_];             // W2^T a21  (self branch, layer 2)
__device__ float g_u2b [H1_];             // W2^T a22  (neighbor branch, layer 2)
__device__ float g_c1;                    // b1 . a11
__device__ float g_c2;                    // b2 . a21
__device__ float g_c2b;                   // b2 . a22
__device__ float g_nbmean[B_];            // per-sample BN stats of layer-1 neighbors
__device__ float g_nbrstd[B_];
__device__ float g_acc[4];                // (sum,sumsq) for x1 ; (sum,sumsq) for x2
// two-digit int8 quantization of W1: per-row scale s, W ~ s*(127*hi + lo)
// stored interleaved along K': byte 2k = hi_k, byte 2k+1 = lo_k  (row stride 2048)
__device__ __align__(16) int8_t g_W1q[H1_ * 2 * F_];   // 512 KB
__device__ float g_sc1[H1_];

// ---------------- generic helpers ----------------
__device__ __forceinline__ float warpSum(float v) {
#pragma unroll
    for (int o = 16; o; o >>= 1) v += __shfl_down_sync(0xffffffffu, v, o);
    return v;
}
__device__ __forceinline__ float warpMax(float v) {
#pragma unroll
    for (int o = 16; o; o >>= 1) v = fmaxf(v, __shfl_xor_sync(0xffffffffu, v, o));
    return v;
}
__device__ __forceinline__ float blockReduce(float v, float* sbuf) {
    int lane = threadIdx.x & 31, warp = threadIdx.x >> 5;
    v = warpSum(v);
    __syncthreads();
    if (lane == 0) sbuf[warp] = v;
    __syncthreads();
    float r = 0.f;
    int nw = blockDim.x >> 5;
    if (warp == 0) { r = (lane < nw) ? sbuf[lane] : 0.f; r = warpSum(r); }
    return r;
}

// ---------------- warp-MMA / async-copy wrappers (plain sm_80+ PTX only) ----------------
__device__ __forceinline__ uint32_t smem_u32(const void* p) {
    uint32_t a;
    asm("{ .reg .u64 t; cvta.to.shared.u64 t, %1; cvt.u32.u64 %0, t; }" : "=r"(a) : "l"(p));
    return a;
}
__device__ __forceinline__ uint32_t sw128(uint32_t x) { return x ^ ((x >> 3) & 0x70); }

__device__ __forceinline__ void cp16(uint32_t dst, const void* src) {
    asm volatile("cp.async.cg.shared.global [%0], [%1], 16;" :: "r"(dst), "l"(src));
}
__device__ __forceinline__ void cp_commit() {
    asm volatile("cp.async.commit_group;" ::: "memory");
}
__device__ __forceinline__ void cp_wait0() {
    asm volatile("cp.async.wait_group 0;" ::: "memory");
}
__device__ __forceinline__ void ldm_x4(uint32_t& r0, uint32_t& r1, uint32_t& r2,
                                       uint32_t& r3, uint32_t addr) {
    asm volatile("ldmatrix.sync.aligned.m8n8.x4.shared.b16 {%0,%1,%2,%3}, [%4];"
                 : "=r"(r0), "=r"(r1), "=r"(r2), "=r"(r3) : "r"(addr));
}
// s8 x s8 -> s32, m16n8k32
__device__ __forceinline__ void mma_s8(int& d0, int& d1, int& d2, int& d3,
                                       uint32_t a0, uint32_t a1, uint32_t a2, uint32_t a3,
                                       uint32_t b0, uint32_t b1) {
    asm volatile(
        "mma.sync.aligned.m16n8k32.row.col.s32.s8.s8.s32 "
        "{%0,%1,%2,%3}, {%4,%5,%6,%7}, {%8,%9}, {%0,%1,%2,%3};"
        : "+r"(d0), "+r"(d1), "+r"(d2), "+r"(d3)
        : "r"(a0), "r"(a1), "r"(a2), "r"(a3), "r"(b0), "r"(b1));
}

// pack two fp32 signs into interleaved A' bytes: (127*sa, sa, 127*sb, sb)
__device__ __forceinline__ uint32_t sgnpack2(float a, float b) {
    int sa = (a > 0.f) - (a < 0.f);
    int sb = (b > 0.f) - (b < 0.f);
    return ((uint32_t)(uint8_t)(int8_t)(127 * sa))
         | ((uint32_t)(uint8_t)(int8_t)sa << 8)
         | ((uint32_t)(uint8_t)(int8_t)(127 * sb) << 16)
         | ((uint32_t)(uint8_t)(int8_t)sb << 24);
}

// ---------------- kernel 0: precompute u1,u2,u2b,c1,c2,c2b; zero accumulators ----------
__global__ void __launch_bounds__(256) pre_kernel(
    const float* __restrict__ W1, const float* __restrict__ a11, const float* __restrict__ b1,
    const float* __restrict__ W2, const float* __restrict__ a21, const float* __restrict__ a22,
    const float* __restrict__ b2)
{
    int tid = threadIdx.x, bid = blockIdx.x;
    __shared__ float s_a[256];
    __shared__ float s_red[32];
    if (bid < 4) {
        s_a[tid] = a11[tid];
        __syncthreads();
        int f = bid * 256 + tid;
        float s0 = 0.f, s1 = 0.f, s2 = 0.f, s3 = 0.f;
#pragma unroll 4
        for (int h = 0; h < H1_; h += 4) {
            s0 += s_a[h]     * W1[(size_t)h * F_ + f];
            s1 += s_a[h + 1] * W1[(size_t)(h + 1) * F_ + f];
            s2 += s_a[h + 2] * W1[(size_t)(h + 2) * F_ + f];
            s3 += s_a[h + 3] * W1[(size_t)(h + 3) * F_ + f];
        }
        g_u1[f] = (s0 + s1) + (s2 + s3);
    } else if (bid == 4) {
        if (tid < 128) s_a[tid] = a21[tid];
        else s_a[tid] = a22[tid - 128];
        __syncthreads();
        int h = tid;
        float p0 = 0.f, p1 = 0.f, q0 = 0.f, q1 = 0.f;
#pragma unroll 4
        for (int c = 0; c < H2_; c += 2) {
            float w0 = W2[(size_t)c * H1_ + h];
            float w1 = W2[(size_t)(c + 1) * H1_ + h];
            p0 += s_a[c] * w0;       p1 += s_a[c + 1] * w1;
            q0 += s_a[128 + c] * w0; q1 += s_a[128 + c + 1] * w1;
        }
        g_u2[h]  = p0 + p1;
        g_u2b[h] = q0 + q1;
    } else {
        float p = b1[tid] * a11[tid];
        float S = blockReduce(p, s_red);
        if (tid == 0) g_c1 = S;
        float q = (tid < H2_) ? b2[tid] * a21[tid] : 0.f;
        float S2 = blockReduce(q, s_red);
        if (tid == 0) g_c2 = S2;
        float r = (tid < H2_) ? b2[tid] * a22[tid] : 0.f;
        float S3 = blockReduce(r, s_red);
        if (tid == 0) g_c2b = S3;
        if (tid < 4) g_acc[tid] = 0.f;
    }
}

// ---------------- quantize W1 to two-digit int8 (per-row 14-bit) ----------------
__global__ void __launch_bounds__(256) wsplit2_kernel(const float* __restrict__ W1)
{
    int row = blockIdx.x, tid = threadIdx.x, lane = tid & 31, warp = tid >> 5;
    __shared__ float s_red[32];
    __shared__ float s_inv;
    float4 v = ((const float4*)(W1 + (size_t)row * F_))[tid];
    float m = fmaxf(fmaxf(fabsf(v.x), fabsf(v.y)), fmaxf(fabsf(v.z), fabsf(v.w)));
    m = warpMax(m);
    if (lane == 0) s_red[warp] = m;
    __syncthreads();
    if (warp == 0) {
        float r = (lane < 8) ? s_red[lane] : 0.f;
        r = warpMax(r);
        if (lane == 0) {
            float s = fmaxf(r, 1e-30f) * (1.f / 16000.f);
            g_sc1[row] = s;
            s_inv = 1.f / s;
        }
    }
    __syncthreads();
    float inv = s_inv;
    uint32_t w[2];
    float vv[4] = {v.x, v.y, v.z, v.w};
#pragma unroll
    for (int j = 0; j < 2; j++) {
        uint32_t p = 0;
#pragma unroll
        for (int q = 0; q < 2; q++) {
            int wi = (int)rintf(vv[2 * j + q] * inv);
            int hi = (int)rintf((float)wi * (1.f / 127.f));
            int lo = wi - 127 * hi;
            p |= ((uint32_t)(uint8_t)(int8_t)hi) << (16 * q);
            p |= ((uint32_t)(uint8_t)(int8_t)lo) << (16 * q + 8);
        }
        w[j] = p;
    }
    uint2 st; st.x = w[0]; st.y = w[1];
    *(uint2*)(g_W1q + (size_t)row * 2048 + tid * 8) = st;
}

// ---------------- layer-1 GEMM: s8 IMMA, virtual K'=2048, single s32 accum ----------
// C[65536,256] = sign(A) @ W1^T + b1,  W ~ s[n]*(127*hi + lo)
// A'[2k] = 127*a_k, A'[2k+1] = a_k ; W'[2k] = hi, W'[2k+1] = lo
// CTA: M=128, N=256; 8 warps 2x4 (warp 64x64). K'-chunk 128 bytes (=64 orig k), 16 iters.
// SMEM: A'[2][16KB] @0, B'[2][32KB] @32768. Total 96KB.
#define SM_TOTAL (32768 + 2 * 32768)

__global__ void __launch_bounds__(256, 1) tc_gemm1(const float* __restrict__ A,
                                                   const float* __restrict__ bias)
{
    extern __shared__ char smem[];
    const uint32_t sb = smem_u32(smem);
    const int tid = threadIdx.x, lane = tid & 31, wid = tid >> 5;
    const int m0 = blockIdx.x * 128;
    const int warp_m = wid >> 2, warp_n = wid & 3;

    const uint32_t offA0 = 0u, offA1 = 16384u;
    const uint32_t offB0 = 32768u, offB1 = 32768u + 32768u;

    int acc[4][8][4];
#pragma unroll
    for (int i = 0; i < 4; i++)
#pragma unroll
        for (int j = 0; j < 8; j++)
#pragma unroll
            for (int k = 0; k < 4; k++) acc[i][j][k] = 0;

    const float* Ag = A + (size_t)m0 * F_;
    const int ar = tid >> 4, ac4 = tid & 15;   // A: 128 rows x 16 float4-groups
    const int br = tid >> 3, bc = tid & 7;     // B': 256 rows (step 32) x 8 16B-groups

    float4 areg[8];
#pragma unroll
    for (int i = 0; i < 8; i++)
        areg[i] = *(const float4*)(Ag + (size_t)(ar + i * 16) * F_ + ac4 * 4);
    {
#pragma unroll
        for (int i = 0; i < 8; i++) {
            int r = br + i * 32;
            cp16(sb + offB0 + sw128((uint32_t)(r * 128 + bc * 16)),
                 g_W1q + (size_t)r * 2048 + bc * 16);
        }
        cp_commit();
    }

    for (int it = 0; it < 16; ++it) {
        const int s = it & 1;
        const uint32_t aOff = s ? offA1 : offA0;
        const uint32_t bOff = s ? offB1 : offB0;

        // STS A': sign-interleave to int8 pairs (byte 2k = 127a, 2k+1 = a)
#pragma unroll
        for (int i = 0; i < 8; i++) {
            float4 v = areg[i];
            uint2 st;
            st.x = sgnpack2(v.x, v.y);
            st.y = sgnpack2(v.z, v.w);
            *(uint2*)(smem + aOff + sw128((uint32_t)((ar + i * 16) * 128 + ac4 * 8))) = st;
        }
        if (it + 1 < 16) {
            int k0 = (it + 1) * 64;
#pragma unroll
            for (int i = 0; i < 8; i++)
                areg[i] = *(const float4*)(Ag + (size_t)(ar + i * 16) * F_ + k0 + ac4 * 4);
        }
        cp_wait0();
        __syncthreads();
        if (it + 1 < 16) {
            int kb = (it + 1) * 128;
            uint32_t bN = s ? offB0 : offB1;
#pragma unroll
            for (int i = 0; i < 8; i++) {
                int r = br + i * 32;
                cp16(sb + bN + sw128((uint32_t)(r * 128 + bc * 16)),
                     g_W1q + (size_t)r * 2048 + kb + bc * 16);
            }
            cp_commit();
        }
        const int mrow = warp_m * 64 + (lane & 15);
        const int nrow = warp_n * 64 + (lane & 7) + ((lane & 16) >> 1);
        const int kbA = ((lane >> 4) & 1) * 16;
        const int kbB = ((lane >> 3) & 1) * 16;
#pragma unroll
        for (int kk = 0; kk < 4; kk++) {       // 4 k32-steps per 128B chunk
            uint32_t a[4][4];
#pragma unroll
            for (int mt = 0; mt < 4; mt++)
                ldm_x4(a[mt][0], a[mt][1], a[mt][2], a[mt][3],
                       sb + aOff + sw128((uint32_t)((mrow + mt * 16) * 128 + kk * 32 + kbA)));
#pragma unroll
            for (int np = 0; np < 4; np++) {
                uint32_t b0, b1, b2, b3;
                ldm_x4(b0, b1, b2, b3,
                       sb + bOff + sw128((uint32_t)((nrow + np * 16) * 128 + kk * 32 + kbB)));
#pragma unroll
                for (int mt = 0; mt < 4; mt++) {
                    mma_s8(acc[mt][2 * np][0], acc[mt][2 * np][1],
                           acc[mt][2 * np][2], acc[mt][2 * np][3],
                           a[mt][0], a[mt][1], a[mt][2], a[mt][3], b0, b1);
                    mma_s8(acc[mt][2 * np + 1][0], acc[mt][2 * np + 1][1],
                           acc[mt][2 * np + 1][2], acc[mt][2 * np + 1][3],
                           a[mt][0], a[mt][1], a[mt][2], a[mt][3], b2, b3);
                }
            }
        }
    }

    // epilogue: C = s[col]*acc + bias[col]
#pragma unroll
    for (int mt = 0; mt < 4; mt++) {
        int r0 = m0 + warp_m * 64 + mt * 16 + (lane >> 2);
        float* C0 = g_nbh + (size_t)r0 * H1_;
        float* C1 = C0 + 8 * H1_;
#pragma unroll
        for (int nt = 0; nt < 8; nt++) {
            int col = warp_n * 64 + nt * 8 + (lane & 3) * 2;
            float2 sc = *(const float2*)(g_sc1 + col);
            float2 bv = *(const float2*)(bias + col);
            float2 o0, o1;
            o0.x = sc.x * (float)acc[mt][nt][0] + bv.x;
            o0.y = sc.y * (float)acc[mt][nt][1] + bv.y;
            o1.x = sc.x * (float)acc[mt][nt][2] + bv.x;
            o1.y = sc.y * (float)acc[mt][nt][3] + bv.y;
            *(float2*)(C0 + col) = o0;
            *(float2*)(C1 + col) = o1;
        }
    }
}

// ---------------- attention layer 1 (float4 score pass) ----------------
__global__ void __launch_bounds__(256) attn1_kernel(
    const float* __restrict__ x, const float* __restrict__ a12)
{
    int b = blockIdx.x, tid = threadIdx.x, lane = tid & 31, warp = tid >> 5;
    __shared__ __align__(16) float s_a12[256];
    __shared__ float s_sc[64];
    __shared__ float s_red[32];
    __shared__ float s_sx;

    s_a12[tid] = a12[tid];

    // self score: sign(x[b]) . u1 + c1
    float p = 0.f;
#pragma unroll
    for (int i = 0; i < 4; i++) {
        int f = tid + i * 256;
        float v = x[(size_t)b * F_ + f];
        v = v / fmaxf(fabsf(v), 1e-12f);
        p += v * g_u1[f];
    }
    float sx = blockReduce(p, s_red);
    if (tid == 0) s_sx = sx + g_c1;
    __syncthreads();

    const float* base = g_nbh + (size_t)b * N_ * H1_;
    const float4* a4 = (const float4*)s_a12;
    float4 aa = a4[lane], ab = a4[lane + 32];
    float lsum = 0.f, lsq = 0.f;
#pragma unroll
    for (int nn = 0; nn < 8; nn++) {
        int n = warp * 8 + nn;
        const float4* row4 = (const float4*)(base + n * H1_);
        float4 va = row4[lane], vb = row4[lane + 32];
        float d = va.x * aa.x + va.y * aa.y + va.z * aa.z + va.w * aa.w
                + vb.x * ab.x + vb.y * ab.y + vb.z * ab.z + vb.w * ab.w;
        lsum += (va.x + va.y + va.z + va.w) + (vb.x + vb.y + vb.z + vb.w);
        lsq  += (va.x * va.x + va.y * va.y + va.z * va.z + va.w * va.w)
              + (vb.x * vb.x + vb.y * vb.y + vb.z * vb.z + vb.w * vb.w);
        d = warpSum(d);
        if (lane == 0) s_sc[n] = d;
    }
    __syncthreads();

    if (warp == 0) {
        float c = s_sx;
        float v0 = c + s_sc[lane];      v0 = v0 > 0.f ? v0 : ALPHA_ * v0;
        float v1 = c + s_sc[lane + 32]; v1 = v1 > 0.f ? v1 : ALPHA_ * v1;
        float m = fmaxf(v0, v1);
#pragma unroll
        for (int o = 16; o; o >>= 1) m = fmaxf(m, __shfl_xor_sync(0xffffffffu, m, o));
        float e0 = expf(v0 - m), e1 = expf(v1 - m);
        float s = e0 + e1;
#pragma unroll
        for (int o = 16; o; o >>= 1) s += __shfl_xor_sync(0xffffffffu, s, o);
        float inv = 1.f / s;
        s_sc[lane] = e0 * inv; s_sc[lane + 32] = e1 * inv;
    }
    __syncthreads();

    float out = 0.f;
#pragma unroll
    for (int n = 0; n < N_; n++) out += s_sc[n] * base[n * H1_ + tid];
    g_x1[(size_t)b * H1_ + tid] = out;

    float S  = blockReduce(lsum, s_red);
    float S2 = blockReduce(lsq, s_red);
    if (tid == 0) {
        float mean = S * (1.f / 16384.f);
        float var  = S2 * (1.f / 16384.f) - mean * mean;
        g_nbmean[b] = mean;
        g_nbrstd[b] = rsqrtf(var + EPS_);
    }
    float So  = blockReduce(out, s_red);
    float So2 = blockReduce(out * out, s_red);
    if (tid == 0) { atomicAdd(&g_acc[0], So); atomicAdd(&g_acc[1], So2); }
}

// ---------------- fused layer-2: scores + softmax + aggregate + W2 projection ----------
__global__ void __launch_bounds__(256) attn2f_kernel(
    const float* __restrict__ W2, const float* __restrict__ b2,
    const float* __restrict__ g1p, const float* __restrict__ be1p)
{
    int b = blockIdx.x, tid = threadIdx.x, lane = tid & 31, warp = tid >> 5;
    __shared__ __align__(16) float s_u2b[256];
    __shared__ __align__(16) float s_agg[256];
    __shared__ float s_sc[64];
    __shared__ float s_red[32];
    __shared__ float s_cb;

    s_u2b[tid] = g_u2b[tid];
    float g1 = *g1p, be1 = *be1p;

    float inv1 = 1.f / (float)(B_ * H1_);
    float m1 = g_acc[0] * inv1;
    float r1 = rsqrtf(g_acc[1] * inv1 - m1 * m1 + EPS_);

    {
        float v = g_x1[(size_t)b * H1_ + tid];
        float xb = fmaxf(g1 * (v - m1) * r1 + be1, 0.f);
        float S = blockReduce(xb * g_u2[tid], s_red);
        if (tid == 0) s_cb = S + g_c2;
    }

    float mn = g_nbmean[b], rs = g_nbrstd[b];
    float sg = g1 * rs;
    float sb2 = be1 - sg * mn;

    const float* base = g_nbh + (size_t)b * N_ * H1_;
    const float4* u4 = (const float4*)s_u2b;
    float4 ua = u4[lane], ub = u4[lane + 32];

#pragma unroll
    for (int nn = 0; nn < 8; nn++) {
        int n = warp * 8 + nn;
        const float4* row4 = (const float4*)(base + n * H1_);
        float4 va = row4[lane], vb = row4[lane + 32];
        va.x = fmaxf(sg * va.x + sb2, 0.f); va.y = fmaxf(sg * va.y + sb2, 0.f);
        va.z = fmaxf(sg * va.z + sb2, 0.f); va.w = fmaxf(sg * va.w + sb2, 0.f);
        vb.x = fmaxf(sg * vb.x + sb2, 0.f); vb.y = fmaxf(sg * vb.y + sb2, 0.f);
        vb.z = fmaxf(sg * vb.z + sb2, 0.f); vb.w = fmaxf(sg * vb.w + sb2, 0.f);
        float d = va.x * ua.x + va.y * ua.y + va.z * ua.z + va.w * ua.w
                + vb.x * ub.x + vb.y * ub.y + vb.z * ub.z + vb.w * ub.w;
        d = warpSum(d);
        if (lane == 0) s_sc[n] = d;
    }
    __syncthreads();

    if (warp == 0) {
        float c = s_cb + g_c2b;
        float v0 = c + s_sc[lane];      v0 = v0 > 0.f ? v0 : ALPHA_ * v0;
        float v1 = c + s_sc[lane + 32]; v1 = v1 > 0.f ? v1 : ALPHA_ * v1;
        float m = fmaxf(v0, v1);
#pragma unroll
        for (int o = 16; o; o >>= 1) m = fmaxf(m, __shfl_xor_sync(0xffffffffu, m, o));
        float e0 = expf(v0 - m), e1 = expf(v1 - m);
        float s = e0 + e1;
#pragma unroll
        for (int o = 16; o; o >>= 1) s += __shfl_xor_sync(0xffffffffu, s, o);
        float inv = 1.f / s;
        s_sc[lane] = e0 * inv; s_sc[lane + 32] = e1 * inv;
    }
    __syncthreads();

    {
        float out = 0.f;
#pragma unroll
        for (int n = 0; n < N_; n++) {
            float v = base[n * H1_ + tid];
            out += s_sc[n] * fmaxf(sg * v + sb2, 0.f);
        }
        s_agg[tid] = out;
    }
    __syncthreads();

    float xv = 0.f;
    if (tid < H2_) {
        const float4* w4 = (const float4*)(W2 + (size_t)tid * H1_);
        const float4* a4 = (const float4*)s_agg;
        float acc = 0.f;
#pragma unroll
        for (int h = 0; h < 64; h++) {
            float4 w = w4[h], a = a4[h];
            acc += w.x * a.x + w.y * a.y + w.z * a.z + w.w * a.w;
        }
        xv = acc + b2[tid];
        g_x2[(size_t)b * H2_ + tid] = xv;
    }
    float S  = blockReduce(tid < H2_ ? xv : 0.f, s_red);
    float S2 = blockReduce(tid < H2_ ? xv * xv : 0.f, s_red);
    if (tid == 0) { atomicAdd(&g_acc[2], S); atomicAdd(&g_acc[3], S2); }
}

// ---------------- final BN + classifier (BN2 stats inline) ----------------
__global__ void __launch_bounds__(128) logits_kernel(
    const float* __restrict__ Wl, const float* __restrict__ bl,
    const float* __restrict__ g2p, const float* __restrict__ be2p,
    float* __restrict__ out)
{
    int b = blockIdx.x, tid = threadIdx.x, lane = tid & 31, warp = tid >> 5;
    __shared__ __align__(16) float s_x[128];
    float inv2 = 1.f / (float)(B_ * H2_);
    float m2 = g_acc[2] * inv2;
    float r2 = rsqrtf(g_acc[3] * inv2 - m2 * m2 + EPS_);
    float g = *g2p, be = *be2p;
    float v = g_x2[(size_t)b * H2_ + tid];
    s_x[tid] = fmaxf(g * (v - m2) * r2 + be, 0.f);
    __syncthreads();
    float4 xv = *(const float4*)&s_x[lane * 4];
#pragma unroll
    for (int cc = 0; cc < 32; cc++) {
        int c = warp * 32 + cc;
        float4 wv = *(const float4*)(Wl + (size_t)c * H2_ + lane * 4);
        float d = wv.x * xv.x + wv.y * xv.y + wv.z * xv.z + wv.w * xv.w;
        d = warpSum(d);
        if (lane == 0) out[(size_t)b * NC_ + c] = d + bl[c];
    }
}

// ---------------- launch ----------------
extern "C" void kernel_launch(void* const* d_in, const int* in_sizes, int n_in,
                              void* d_out, int out_size) {
    (void)in_sizes; (void)n_in; (void)out_size;
    const float* x   = (const float*)d_in[0];
    const float* nb  = (const float*)d_in[1];
    const float* W1  = (const float*)d_in[2];
    const float* b1  = (const float*)d_in[3];
    const float* a11 = (const float*)d_in[4];
    const float* a12 = (const float*)d_in[5];
    const float* g1  = (const float*)d_in[6];
    const float* be1 = (const float*)d_in[7];
    const float* W2  = (const float*)d_in[8];
    const float* b2  = (const float*)d_in[9];
    const float* a21 = (const float*)d_in[10];
    const float* a22 = (const float*)d_in[11];
    const float* g2  = (const float*)d_in[12];
    const float* be2 = (const float*)d_in[13];
    const float* Wl  = (const float*)d_in[14];
    const float* bl  = (const float*)d_in[15];
    float* out = (float*)d_out;

    cudaFuncSetAttribute(tc_gemm1, cudaFuncAttributeMaxDynamicSharedMemorySize, SM_TOTAL);

    pre_kernel<<<6, 256>>>(W1, a11, b1, W2, a21, a22, b2);
    wsplit2_kernel<<<H1_, 256>>>(W1);
    tc_gemm1<<<512, 256, SM_TOTAL>>>(nb, b1);
    attn1_kernel<<<B_, 256>>>(x, a12);
    attn2f_kernel<<<B_, 256>>>(W2, b2, g1, be1);
    logits_kernel<<<B_, 128>>>(Wl, bl, g2, be2, out);
}

// round 16
// speedup vs baseline: 2.9867x; 2.9867x over previous
#include <cuda_runtime.h>
#include <cuda_fp16.h>
#include <cstdint>
#include <cstddef>

#define B_    1024
#define N_    64
#define F_    1024
#define H1_   256
#define H2_   128
#define NC_   128
#define ALPHA_ 0.2f
#define EPS_  1e-5f

// ---------------- scratch (device globals; no allocations) ----------------
__device__ float g_nbh [B_ * N_ * H1_];   // 64 MB  layer-1 neighbor features
__device__ float g_x1  [B_ * H1_];
__device__ float g_x2  [B_ * H2_];
__device__ float g_u1  [F_];              // W1^T a11
__device__ float g_u2  [H1_];             // W2^T a21  (self branch, layer 2)
__device__ float g_u2b [H1_];             // W2^T a22  (neighbor branch, layer 2)
__device__ float g_c1;                    // b1 . a11
__device__ float g_c2;                    // b2 . a21
__device__ float g_c2b;                   // b2 . a22
__device__ float g_nbmean[B_];            // per-sample BN stats of layer-1 neighbors
__device__ float g_nbrstd[B_];
__device__ float g_acc[4];                // (sum,sumsq) for x1 ; (sum,sumsq) for x2
// fp16 copy of W1 (single digit — quantization error ~2^-11 rel, attenuated downstream)
__device__ __align__(16) __half g_W1h[H1_ * F_];   // 512 KB

// ---------------- generic helpers ----------------
__device__ __forceinline__ float warpSum(float v) {
#pragma unroll
    for (int o = 16; o; o >>= 1) v += __shfl_down_sync(0xffffffffu, v, o);
    return v;
}
__device__ __forceinline__ float blockReduce(float v, float* sbuf) {
    int lane = threadIdx.x & 31, warp = threadIdx.x >> 5;
    v = warpSum(v);
    __syncthreads();
    if (lane == 0) sbuf[warp] = v;
    __syncthreads();
    float r = 0.f;
    int nw = blockDim.x >> 5;
    if (warp == 0) { r = (lane < nw) ? sbuf[lane] : 0.f; r = warpSum(r); }
    return r;
}

// ---------------- warp-MMA / async-copy wrappers (plain sm_80+ PTX only) ----------------
__device__ __forceinline__ uint32_t smem_u32(const void* p) {
    uint32_t a;
    asm("{ .reg .u64 t; cvta.to.shared.u64 t, %1; cvt.u32.u64 %0, t; }" : "=r"(a) : "l"(p));
    return a;
}
__device__ __forceinline__ uint32_t sw128(uint32_t x) { return x ^ ((x >> 3) & 0x70); }

__device__ __forceinline__ void cp16(uint32_t dst, const void* src) {
    asm volatile("cp.async.cg.shared.global [%0], [%1], 16;" :: "r"(dst), "l"(src));
}
__device__ __forceinline__ void cp_commit() {
    asm volatile("cp.async.commit_group;" ::: "memory");
}
__device__ __forceinline__ void cp_wait0() {
    asm volatile("cp.async.wait_group 0;" ::: "memory");
}
__device__ __forceinline__ void ldm_x4(uint32_t& r0, uint32_t& r1, uint32_t& r2,
                                       uint32_t& r3, uint32_t addr) {
    asm volatile("ldmatrix.sync.aligned.m8n8.x4.shared.b16 {%0,%1,%2,%3}, [%4];"
                 : "=r"(r0), "=r"(r1), "=r"(r2), "=r"(r3) : "r"(addr));
}
__device__ __forceinline__ void mma_f16(float& d0, float& d1, float& d2, float& d3,
                                        uint32_t a0, uint32_t a1, uint32_t a2, uint32_t a3,
                                        uint32_t b0, uint32_t b1) {
    asm volatile(
        "mma.sync.aligned.m16n8k16.row.col.f32.f16.f16.f32 "
        "{%0,%1,%2,%3}, {%4,%5,%6,%7}, {%8,%9}, {%0,%1,%2,%3};"
        : "+f"(d0), "+f"(d1), "+f"(d2), "+f"(d3)
        : "r"(a0), "r"(a1), "r"(a2), "r"(a3), "r"(b0), "r"(b1));
}

// exact sign(v) matching v / max(|v|, 1e-12)
__device__ __forceinline__ float sgn_(float v) {
    float r = __int_as_float((__float_as_int(v) & 0x80000000u) | 0x3f800000u);
    return fabsf(v) >= 1e-12f ? r : v * 1e12f;
}

// ---------------- kernel 0: precompute u1,u2,u2b,c1,c2,c2b; zero accumulators ----------
__global__ void __launch_bounds__(256) pre_kernel(
    const float* __restrict__ W1, const float* __restrict__ a11, const float* __restrict__ b1,
    const float* __restrict__ W2, const float* __restrict__ a21, const float* __restrict__ a22,
    const float* __restrict__ b2)
{
    int tid = threadIdx.x, bid = blockIdx.x;
    __shared__ float s_a[256];
    __shared__ float s_red[32];
    if (bid < 4) {
        s_a[tid] = a11[tid];
        __syncthreads();
        int f = bid * 256 + tid;
        float s0 = 0.f, s1 = 0.f, s2 = 0.f, s3 = 0.f;
#pragma unroll 4
        for (int h = 0; h < H1_; h += 4) {
            s0 += s_a[h]     * W1[(size_t)h * F_ + f];
            s1 += s_a[h + 1] * W1[(size_t)(h + 1) * F_ + f];
            s2 += s_a[h + 2] * W1[(size_t)(h + 2) * F_ + f];
            s3 += s_a[h + 3] * W1[(size_t)(h + 3) * F_ + f];
        }
        g_u1[f] = (s0 + s1) + (s2 + s3);
    } else if (bid == 4) {
        if (tid < 128) s_a[tid] = a21[tid];
        else s_a[tid] = a22[tid - 128];
        __syncthreads();
        int h = tid;
        float p0 = 0.f, p1 = 0.f, q0 = 0.f, q1 = 0.f;
#pragma unroll 4
        for (int c = 0; c < H2_; c += 2) {
            float w0 = W2[(size_t)c * H1_ + h];
            float w1 = W2[(size_t)(c + 1) * H1_ + h];
            p0 += s_a[c] * w0;       p1 += s_a[c + 1] * w1;
            q0 += s_a[128 + c] * w0; q1 += s_a[128 + c + 1] * w1;
        }
        g_u2[h]  = p0 + p1;
        g_u2b[h] = q0 + q1;
    } else {
        float p = b1[tid] * a11[tid];
        float S = blockReduce(p, s_red);
        if (tid == 0) g_c1 = S;
        float q = (tid < H2_) ? b2[tid] * a21[tid] : 0.f;
        float S2 = blockReduce(q, s_red);
        if (tid == 0) g_c2 = S2;
        float r = (tid < H2_) ? b2[tid] * a22[tid] : 0.f;
        float S3 = blockReduce(r, s_red);
        if (tid == 0) g_c2b = S3;
        if (tid < 4) g_acc[tid] = 0.f;
    }
}

// ---------------- convert W1 to fp16 ----------------
__global__ void __launch_bounds__(256) wsplit_kernel(const float* __restrict__ W1)
{
    int row = blockIdx.x;
    int t = threadIdx.x;
    float4 v = ((const float4*)(W1 + (size_t)row * F_))[t];
    __half2* dh = (__half2*)(g_W1h + (size_t)row * F_ + t * 4);
    dh[0] = __halves2half2(__float2half_rn(v.x), __float2half_rn(v.y));
    dh[1] = __halves2half2(__float2half_rn(v.z), __float2half_rn(v.w));
}

// ---------------- layer-1 GEMM on warp MMA (fp16, fp32 accum) ----------------
// C[65536,256] = sign(A)[65536,1024] @ W1h^T + b1
// CTA: M=128, N=256. 8 warps in 2(M) x 4(N): warp tile 64x64.
// K-chunk per iter = 64 fp16 (128B rows, SW128). 16 iters.
// SMEM: A[2][16KB] @ 0, B[2][32KB] @ 32KB. Total 96KB.
#define SM_TOTAL (32768 + 2 * 32768)

__global__ void __launch_bounds__(256, 1) tc_gemm1(const float* __restrict__ A,
                                                   const float* __restrict__ bias)
{
    extern __shared__ char smem[];
    const uint32_t sb = smem_u32(smem);
    const int tid = threadIdx.x, lane = tid & 31, wid = tid >> 5;
    const int m0 = blockIdx.x * 128;
    const int warp_m = wid >> 2, warp_n = wid & 3;

    const uint32_t offA0 = 0u, offA1 = 16384u;
    const uint32_t offB0 = 32768u, offB1 = 32768u + 32768u;

    float acc[4][8][4];
#pragma unroll
    for (int i = 0; i < 4; i++)
#pragma unroll
        for (int j = 0; j < 8; j++)
#pragma unroll
            for (int k = 0; k < 4; k++) acc[i][j][k] = 0.f;

    const float* Ag = A + (size_t)m0 * F_;
    const int ar = tid >> 4, ac4 = tid & 15;   // A: 128 rows x 16 float4-groups
    const int br = tid >> 3, bc = tid & 7;     // B: 256 rows (step 32) x 8 16B-groups

    float4 areg[8];
#pragma unroll
    for (int i = 0; i < 8; i++)
        areg[i] = *(const float4*)(Ag + (size_t)(ar + i * 16) * F_ + ac4 * 4);
    {
#pragma unroll
        for (int i = 0; i < 8; i++) {
            int r = br + i * 32;
            cp16(sb + offB0 + sw128((uint32_t)(r * 128 + bc * 16)),
                 g_W1h + (size_t)r * F_ + bc * 8);
        }
        cp_commit();
    }

    for (int it = 0; it < 16; ++it) {
        const int s = it & 1;
        const uint32_t aOff = s ? offA1 : offA0;
        const uint32_t bOff = s ? offB1 : offB0;

        // STS A: convert to sign fp16, swizzled
#pragma unroll
        for (int i = 0; i < 8; i++) {
            float4 v = areg[i];
            __half2 p0 = __halves2half2(__float2half_rn(sgn_(v.x)),
                                        __float2half_rn(sgn_(v.y)));
            __half2 p1 = __halves2half2(__float2half_rn(sgn_(v.z)),
                                        __float2half_rn(sgn_(v.w)));
            uint2 st; st.x = *(uint32_t*)&p0; st.y = *(uint32_t*)&p1;
            *(uint2*)(smem + aOff + sw128((uint32_t)((ar + i * 16) * 128 + ac4 * 8))) = st;
        }
        if (it + 1 < 16) {
            int k0 = (it + 1) * 64;
#pragma unroll
            for (int i = 0; i < 8; i++)
                areg[i] = *(const float4*)(Ag + (size_t)(ar + i * 16) * F_ + k0 + ac4 * 4);
        }
        cp_wait0();
        __syncthreads();
        if (it + 1 < 16) {
            int k0 = (it + 1) * 64;
            uint32_t bN = s ? offB0 : offB1;
#pragma unroll
            for (int i = 0; i < 8; i++) {
                int r = br + i * 32;
                cp16(sb + bN + sw128((uint32_t)(r * 128 + bc * 16)),
                     g_W1h + (size_t)r * F_ + k0 + bc * 8);
            }
            cp_commit();
        }
        const int mrow = warp_m * 64 + (lane & 15);
        const int nrow = warp_n * 64 + (lane & 7) + ((lane & 16) >> 1);
        const int kbA = ((lane >> 4) & 1) * 16;
        const int kbB = ((lane >> 3) & 1) * 16;
#pragma unroll
        for (int kk = 0; kk < 4; kk++) {
            uint32_t a[4][4];
#pragma unroll
            for (int mt = 0; mt < 4; mt++)
                ldm_x4(a[mt][0], a[mt][1], a[mt][2], a[mt][3],
                       sb + aOff + sw128((uint32_t)((mrow + mt * 16) * 128 + kk * 32 + kbA)));
#pragma unroll
            for (int np = 0; np < 4; np++) {
                uint32_t b0, b1, b2, b3;
                ldm_x4(b0, b1, b2, b3,
                       sb + bOff + sw128((uint32_t)((nrow + np * 16) * 128 + kk * 32 + kbB)));
#pragma unroll
                for (int mt = 0; mt < 4; mt++) {
                    mma_f16(acc[mt][2 * np][0], acc[mt][2 * np][1],
                            acc[mt][2 * np][2], acc[mt][2 * np][3],
                            a[mt][0], a[mt][1], a[mt][2], a[mt][3], b0, b1);
                    mma_f16(acc[mt][2 * np + 1][0], acc[mt][2 * np + 1][1],
                            acc[mt][2 * np + 1][2], acc[mt][2 * np + 1][3],
                            a[mt][0], a[mt][1], a[mt][2], a[mt][3], b2, b3);
                }
            }
        }
    }

    // ---- epilogue: bias + store ----
#pragma unroll
    for (int mt = 0; mt < 4; mt++) {
        int r0 = m0 + warp_m * 64 + mt * 16 + (lane >> 2);
        float* C0 = g_nbh + (size_t)r0 * H1_;
        float* C1 = C0 + 8 * H1_;
#pragma unroll
        for (int nt = 0; nt < 8; nt++) {
            int col = warp_n * 64 + nt * 8 + (lane & 3) * 2;
            float2 bv = *(const float2*)(bias + col);
            float2 o0, o1;
            o0.x = acc[mt][nt][0] + bv.x; o0.y = acc[mt][nt][1] + bv.y;
            o1.x = acc[mt][nt][2] + bv.x; o1.y = acc[mt][nt][3] + bv.y;
            *(float2*)(C0 + col) = o0;
            *(float2*)(C1 + col) = o1;
        }
    }
}

// ---------------- attention layer 1 (float4 score pass) ----------------
__global__ void __launch_bounds__(256) attn1_kernel(
    const float* __restrict__ x, const float* __restrict__ a12)
{
    int b = blockIdx.x, tid = threadIdx.x, lane = tid & 31, warp = tid >> 5;
    __shared__ __align__(16) float s_a12[256];
    __shared__ float s_sc[64];
    __shared__ float s_red[32];
    __shared__ float s_sx;

    s_a12[tid] = a12[tid];

    // self score: sign(x[b]) . u1 + c1
    float p = 0.f;
#pragma unroll
    for (int i = 0; i < 4; i++) {
        int f = tid + i * 256;
        float v = x[(size_t)b * F_ + f];
        v = v / fmaxf(fabsf(v), 1e-12f);
        p += v * g_u1[f];
    }
    float sx = blockReduce(p, s_red);
    if (tid == 0) s_sx = sx + g_c1;
    __syncthreads();

    const float* base = g_nbh + (size_t)b * N_ * H1_;
    const float4* a4 = (const float4*)s_a12;
    float4 aa = a4[lane], ab = a4[lane + 32];
    float lsum = 0.f, lsq = 0.f;
#pragma unroll
    for (int nn = 0; nn < 8; nn++) {
        int n = warp * 8 + nn;
        const float4* row4 = (const float4*)(base + n * H1_);
        float4 va = row4[lane], vb = row4[lane + 32];
        float d = va.x * aa.x + va.y * aa.y + va.z * aa.z + va.w * aa.w
                + vb.x * ab.x + vb.y * ab.y + vb.z * ab.z + vb.w * ab.w;
        lsum += (va.x + va.y + va.z + va.w) + (vb.x + vb.y + vb.z + vb.w);
        lsq  += (va.x * va.x + va.y * va.y + va.z * va.z + va.w * va.w)
              + (vb.x * vb.x + vb.y * vb.y + vb.z * vb.z + vb.w * vb.w);
        d = warpSum(d);
        if (lane == 0) s_sc[n] = d;
    }
    __syncthreads();

    if (warp == 0) {
        float c = s_sx;
        float v0 = c + s_sc[lane];      v0 = v0 > 0.f ? v0 : ALPHA_ * v0;
        float v1 = c + s_sc[lane + 32]; v1 = v1 > 0.f ? v1 : ALPHA_ * v1;
        float m = fmaxf(v0, v1);
#pragma unroll
        for (int o = 16; o; o >>= 1) m = fmaxf(m, __shfl_xor_sync(0xffffffffu, m, o));
        float e0 = expf(v0 - m), e1 = expf(v1 - m);
        float s = e0 + e1;
#pragma unroll
        for (int o = 16; o; o >>= 1) s += __shfl_xor_sync(0xffffffffu, s, o);
        float inv = 1.f / s;
        s_sc[lane] = e0 * inv; s_sc[lane + 32] = e1 * inv;
    }
    __syncthreads();

    float out = 0.f;
#pragma unroll
    for (int n = 0; n < N_; n++) out += s_sc[n] * base[n * H1_ + tid];
    g_x1[(size_t)b * H1_ + tid] = out;

    float S  = blockReduce(lsum, s_red);
    float S2 = blockReduce(lsq, s_red);
    if (tid == 0) {
        float mean = S * (1.f / 16384.f);
        float var  = S2 * (1.f / 16384.f) - mean * mean;
        g_nbmean[b] = mean;
        g_nbrstd[b] = rsqrtf(var + EPS_);
    }
    float So  = blockReduce(out, s_red);
    float So2 = blockReduce(out * out, s_red);
    if (tid == 0) { atomicAdd(&g_acc[0], So); atomicAdd(&g_acc[1], So2); }
}

// ---------------- fused layer-2: scores + softmax + aggregate + W2 projection ----------
__global__ void __launch_bounds__(256) attn2f_kernel(
    const float* __restrict__ W2, const float* __restrict__ b2,
    const float* __restrict__ g1p, const float* __restrict__ be1p)
{
    int b = blockIdx.x, tid = threadIdx.x, lane = tid & 31, warp = tid >> 5;
    __shared__ __align__(16) float s_u2b[256];
    __shared__ __align__(16) float s_agg[256];
    __shared__ float s_sc[64];
    __shared__ float s_red[32];
    __shared__ float s_cb;

    s_u2b[tid] = g_u2b[tid];
    float g1 = *g1p, be1 = *be1p;

    float inv1 = 1.f / (float)(B_ * H1_);
    float m1 = g_acc[0] * inv1;
    float r1 = rsqrtf(g_acc[1] * inv1 - m1 * m1 + EPS_);

    {
        float v = g_x1[(size_t)b * H1_ + tid];
        float xb = fmaxf(g1 * (v - m1) * r1 + be1, 0.f);
        float S = blockReduce(xb * g_u2[tid], s_red);
        if (tid == 0) s_cb = S + g_c2;
    }

    float mn = g_nbmean[b], rs = g_nbrstd[b];
    float sg = g1 * rs;
    float sb2 = be1 - sg * mn;

    const float* base = g_nbh + (size_t)b * N_ * H1_;
    const float4* u4 = (const float4*)s_u2b;
    float4 ua = u4[lane], ub = u4[lane + 32];

#pragma unroll
    for (int nn = 0; nn < 8; nn++) {
        int n = warp * 8 + nn;
        const float4* row4 = (const float4*)(base + n * H1_);
        float4 va = row4[lane], vb = row4[lane + 32];
        va.x = fmaxf(sg * va.x + sb2, 0.f); va.y = fmaxf(sg * va.y + sb2, 0.f);
        va.z = fmaxf(sg * va.z + sb2, 0.f); va.w = fmaxf(sg * va.w + sb2, 0.f);
        vb.x = fmaxf(sg * vb.x + sb2, 0.f); vb.y = fmaxf(sg * vb.y + sb2, 0.f);
        vb.z = fmaxf(sg * vb.z + sb2, 0.f); vb.w = fmaxf(sg * vb.w + sb2, 0.f);
        float d = va.x * ua.x + va.y * ua.y + va.z * ua.z + va.w * ua.w
                + vb.x * ub.x + vb.y * ub.y + vb.z * ub.z + vb.w * ub.w;
        d = warpSum(d);
        if (lane == 0) s_sc[n] = d;
    }
    __syncthreads();

    if (warp == 0) {
        float c = s_cb + g_c2b;
        float v0 = c + s_sc[lane];      v0 = v0 > 0.f ? v0 : ALPHA_ * v0;
        float v1 = c + s_sc[lane + 32]; v1 = v1 > 0.f ? v1 : ALPHA_ * v1;
        float m = fmaxf(v0, v1);
#pragma unroll
        for (int o = 16; o; o >>= 1) m = fmaxf(m, __shfl_xor_sync(0xffffffffu, m, o));
        float e0 = expf(v0 - m), e1 = expf(v1 - m);
        float s = e0 + e1;
#pragma unroll
        for (int o = 16; o; o >>= 1) s += __shfl_xor_sync(0xffffffffu, s, o);
        float inv = 1.f / s;
        s_sc[lane] = e0 * inv; s_sc[lane + 32] = e1 * inv;
    }
    __syncthreads();

    {
        float out = 0.f;
#pragma unroll
        for (int n = 0; n < N_; n++) {
            float v = base[n * H1_ + tid];
            out += s_sc[n] * fmaxf(sg * v + sb2, 0.f);
        }
        s_agg[tid] = out;
    }
    __syncthreads();

    float xv = 0.f;
    if (tid < H2_) {
        const float4* w4 = (const float4*)(W2 + (size_t)tid * H1_);
        const float4* a4 = (const float4*)s_agg;
        float acc = 0.f;
#pragma unroll
        for (int h = 0; h < 64; h++) {
            float4 w = w4[h], a = a4[h];
            acc += w.x * a.x + w.y * a.y + w.z * a.z + w.w * a.w;
        }
        xv = acc + b2[tid];
        g_x2[(size_t)b * H2_ + tid] = xv;
    }
    float S  = blockReduce(tid < H2_ ? xv : 0.f, s_red);
    float S2 = blockReduce(tid < H2_ ? xv * xv : 0.f, s_red);
    if (tid == 0) { atomicAdd(&g_acc[2], S); atomicAdd(&g_acc[3], S2); }
}

// ---------------- final BN + classifier (BN2 stats inline) ----------------
__global__ void __launch_bounds__(128) logits_kernel(
    const float* __restrict__ Wl, const float* __restrict__ bl,
    const float* __restrict__ g2p, const float* __restrict__ be2p,
    float* __restrict__ out)
{
    int b = blockIdx.x, tid = threadIdx.x, lane = tid & 31, warp = tid >> 5;
    __shared__ __align__(16) float s_x[128];
    float inv2 = 1.f / (float)(B_ * H2_);
    float m2 = g_acc[2] * inv2;
    float r2 = rsqrtf(g_acc[3] * inv2 - m2 * m2 + EPS_);
    float g = *g2p, be = *be2p;
    float v = g_x2[(size_t)b * H2_ + tid];
    s_x[tid] = fmaxf(g * (v - m2) * r2 + be, 0.f);
    __syncthreads();
    float4 xv = *(const float4*)&s_x[lane * 4];
#pragma unroll
    for (int cc = 0; cc < 32; cc++) {
        int c = warp * 32 + cc;
        float4 wv = *(const float4*)(Wl + (size_t)c * H2_ + lane * 4);
        float d = wv.x * xv.x + wv.y * xv.y + wv.z * xv.z + wv.w * xv.w;
        d = warpSum(d);
        if (lane == 0) out[(size_t)b * NC_ + c] = d + bl[c];
    }
}

// ---------------- launch ----------------
extern "C" void kernel_launch(void* const* d_in, const int* in_sizes, int n_in,
                              void* d_out, int out_size) {
    (void)in_sizes; (void)n_in; (void)out_size;
    const float* x   = (const float*)d_in[0];
    const float* nb  = (const float*)d_in[1];
    const float* W1  = (const float*)d_in[2];
    const float* b1  = (const float*)d_in[3];
    const float* a11 = (const float*)d_in[4];
    const float* a12 = (const float*)d_in[5];
    const float* g1  = (const float*)d_in[6];
    const float* be1 = (const float*)d_in[7];
    const float* W2  = (const float*)d_in[8];
    const float* b2  = (const float*)d_in[9];
    const float* a21 = (const float*)d_in[10];
    const float* a22 = (const float*)d_in[11];
    const float* g2  = (const float*)d_in[12];
    const float* be2 = (const float*)d_in[13];
    const float* Wl  = (const float*)d_in[14];
    const float* bl  = (const float*)d_in[15];
    float* out = (float*)d_out;

    cudaFuncSetAttribute(tc_gemm1, cudaFuncAttributeMaxDynamicSharedMemorySize, SM_TOTAL);

    pre_kernel<<<6, 256>>>(W1, a11, b1, W2, a21, a22, b2);
    wsplit_kernel<<<H1_, 256>>>(W1);
    tc_gemm1<<<512, 256, SM_TOTAL>>>(nb, b1);
    attn1_kernel<<<B_, 256>>>(x, a12);
    attn2f_kernel<<<B_, 256>>>(W2, b2, g1, be1);
    logits_kernel<<<B_, 128>>>(Wl, bl, g2, be2, out);
}